// round 13
// baseline (speedup 1.0000x reference)
#include <cuda_runtime.h>
#include <cuda_fp16.h>
#include <cstdint>
#include <math.h>

#define Bv   8
#define Tv   2048
#define Cv   1024
#define Hv   16
#define Nv   64
#define FFNv 3584
#define Mv   (Bv*Tv)          /* 16384 tokens */
#define EPSv 1e-5f

// ---------------------------------------------------------------------------
// Scratch pool
// ---------------------------------------------------------------------------
#define MC   ((size_t)Mv * Cv)
#define MF   ((size_t)Mv * FFNv)
#define WCC  ((size_t)Cv * Cv)
#define WFC  ((size_t)FFNv * Cv)
__device__ float g_pool[16 * MC + MF + 6 * WCC + 2 * WFC];

#define OFF_X0   (0*MC)
#define OFF_XR   (2*MC)
#define OFF_XK   (3*MC)
#define OFF_XV   (4*MC)
#define OFF_XG   (5*MC)
#define OFF_R    (6*MC)
#define OFF_K    (7*MC)
#define OFF_V    (8*MC)
#define OFF_G    (9*MC)
#define OFF_Y    (10*MC)
#define OFF_YM   (11*MC)
#define OFF_XK2  (13*MC)
#define OFF_XR2  (14*MC)
#define OFF_SR   (15*MC)
#define OFF_KF   (16*MC)
#define OFF_W    (16*MC + MF)
#define OFF_WR   (OFF_W + 0*WCC)
#define OFF_WK   (OFF_W + 1*WCC)
#define OFF_WV   (OFF_W + 2*WCC)
#define OFF_WG   (OFF_W + 3*WCC)
#define OFF_WO   (OFF_W + 4*WCC)
#define OFF_FWR  (OFF_W + 5*WCC)
#define OFF_FWK  (OFF_W + 6*WCC)
#define OFF_FWV  (OFF_W + 6*WCC + WFC)

// ---------------------------------------------------------------------------
// helpers
// ---------------------------------------------------------------------------
__device__ __forceinline__ float4 block_reduce4(float a, float b, float c, float d,
                                                float* shm /*32*/)
{
#pragma unroll
    for (int o = 16; o; o >>= 1) {
        a += __shfl_xor_sync(0xffffffffu, a, o);
        b += __shfl_xor_sync(0xffffffffu, b, o);
        c += __shfl_xor_sync(0xffffffffu, c, o);
        d += __shfl_xor_sync(0xffffffffu, d, o);
    }
    int w = threadIdx.x >> 5;
    if ((threadIdx.x & 31) == 0) { shm[w] = a; shm[8+w] = b; shm[16+w] = c; shm[24+w] = d; }
    __syncthreads();
    a = shm[0]; b = shm[8]; c = shm[16]; d = shm[24];
#pragma unroll
    for (int i = 1; i < 8; i++) {
        a += shm[i]; b += shm[8+i]; c += shm[16+i]; d += shm[24+i];
    }
    return make_float4(a, b, c, d);
}

__device__ __forceinline__ void st_half4(__half* p, size_t i4, float4 v)
{
    __half2 lo = __floats2half2_rn(v.x, v.y);
    __half2 hi = __floats2half2_rn(v.z, v.w);
    uint2 u;
    u.x = *reinterpret_cast<unsigned*>(&lo);
    u.y = *reinterpret_cast<unsigned*>(&hi);
    *reinterpret_cast<uint2*>(p + i4 * 4) = u;
}

__device__ __forceinline__ void cp_async16(void* smem, const void* gptr)
{
    unsigned saddr = (unsigned)__cvta_generic_to_shared(smem);
    asm volatile("cp.async.ca.shared.global [%0], [%1], 16;\n" :: "r"(saddr), "l"(gptr));
}
#define CP_COMMIT() asm volatile("cp.async.commit_group;\n" ::: "memory")
#define CP_WAIT0()  asm volatile("cp.async.wait_group 0;\n" ::: "memory")
#define CP_WAIT1()  asm volatile("cp.async.wait_group 1;\n" ::: "memory")

#define LDSM4(r0, r1, r2, r3, addr) \
    asm volatile("ldmatrix.sync.aligned.m8n8.x4.shared.b16 {%0,%1,%2,%3}, [%4];" \
                 : "=r"(r0), "=r"(r1), "=r"(r2), "=r"(r3) : "r"(addr))

// ---------------------------------------------------------------------------
// all-weights fp32 -> fp16 in one launch (grid.z selects tensor)
// ---------------------------------------------------------------------------
__global__ __launch_bounds__(256) void cvtw_all_kernel(
    const float* __restrict__ i0, const float* __restrict__ i1,
    const float* __restrict__ i2, const float* __restrict__ i3,
    const float* __restrict__ i4, const float* __restrict__ i5,
    const float* __restrict__ i6, const float* __restrict__ i7,
    __half* __restrict__ o0, __half* __restrict__ o1,
    __half* __restrict__ o2, __half* __restrict__ o3,
    __half* __restrict__ o4, __half* __restrict__ o5,
    __half* __restrict__ o6, __half* __restrict__ o7,
    int nCC4, int nFC4)
{
    int z = blockIdx.z;
    const float* in; __half* outp; int n4;
    switch (z) {
        case 0: in = i0; outp = o0; n4 = nCC4; break;
        case 1: in = i1; outp = o1; n4 = nCC4; break;
        case 2: in = i2; outp = o2; n4 = nCC4; break;
        case 3: in = i3; outp = o3; n4 = nCC4; break;
        case 4: in = i4; outp = o4; n4 = nCC4; break;
        case 5: in = i5; outp = o5; n4 = nCC4; break;
        case 6: in = i6; outp = o6; n4 = nFC4; break;
        default: in = i7; outp = o7; n4 = nFC4; break;
    }
    int idx = blockIdx.x * blockDim.x + threadIdx.x;
    if (idx >= n4) return;
    float4 v = ((const float4*)in)[idx];
    st_half4(outp, idx, v);
}

// ---------------------------------------------------------------------------
// Fused LN0+LN1+token-shift-mix4 -> half outputs (r8 block-per-token version)
// ---------------------------------------------------------------------------
__global__ __launch_bounds__(256) void ln01mix4_kernel(
    const float* __restrict__ x,
    const float* __restrict__ w0, const float* __restrict__ b0,
    const float* __restrict__ w1, const float* __restrict__ b1,
    const float* __restrict__ tmk, const float* __restrict__ tmv,
    const float* __restrict__ tmr, const float* __restrict__ tmg,
    float* __restrict__ x0,
    __half* __restrict__ xk, __half* __restrict__ xv,
    __half* __restrict__ xr, __half* __restrict__ xg)
{
    __shared__ float shm1[32], shm2[32];
    int m = blockIdx.x, tid = threadIdx.x;
    bool hp = (m % Tv) != 0;

    const float4 vc = ((const float4*)(x + (size_t)m * Cv))[tid];
    float4 vp = make_float4(0.f, 0.f, 0.f, 0.f);
    if (hp) vp = ((const float4*)(x + (size_t)(m - 1) * Cv))[tid];

    float4 r0 = block_reduce4(
        vc.x + vc.y + vc.z + vc.w,
        vc.x*vc.x + vc.y*vc.y + vc.z*vc.z + vc.w*vc.w,
        vp.x + vp.y + vp.z + vp.w,
        vp.x*vp.x + vp.y*vp.y + vp.z*vp.z + vp.w*vp.w, shm1);

    float muc = r0.x * (1.0f / Cv);
    float ivc = rsqrtf(r0.y * (1.0f / Cv) - muc * muc + EPSv);
    float mup = r0.z * (1.0f / Cv);
    float ivp = rsqrtf(r0.w * (1.0f / Cv) - mup * mup + EPSv);

    const float4 w0v = ((const float4*)w0)[tid];
    const float4 b0v = ((const float4*)b0)[tid];
    float4 c0, p0;
    c0.x = (vc.x - muc) * ivc * w0v.x + b0v.x;
    c0.y = (vc.y - muc) * ivc * w0v.y + b0v.y;
    c0.z = (vc.z - muc) * ivc * w0v.z + b0v.z;
    c0.w = (vc.w - muc) * ivc * w0v.w + b0v.w;
    p0.x = (vp.x - mup) * ivp * w0v.x + b0v.x;
    p0.y = (vp.y - mup) * ivp * w0v.y + b0v.y;
    p0.z = (vp.z - mup) * ivp * w0v.z + b0v.z;
    p0.w = (vp.w - mup) * ivp * w0v.w + b0v.w;
    ((float4*)(x0 + (size_t)m * Cv))[tid] = c0;

    float4 r1 = block_reduce4(
        c0.x + c0.y + c0.z + c0.w,
        c0.x*c0.x + c0.y*c0.y + c0.z*c0.z + c0.w*c0.w,
        p0.x + p0.y + p0.z + p0.w,
        p0.x*p0.x + p0.y*p0.y + p0.z*p0.z + p0.w*p0.w, shm2);

    muc = r1.x * (1.0f / Cv);
    ivc = rsqrtf(r1.y * (1.0f / Cv) - muc * muc + EPSv);
    mup = r1.z * (1.0f / Cv);
    ivp = rsqrtf(r1.w * (1.0f / Cv) - mup * mup + EPSv);

    const float4 w1v = ((const float4*)w1)[tid];
    const float4 b1v = ((const float4*)b1)[tid];
    float4 xnc, xnp;
    xnc.x = (c0.x - muc) * ivc * w1v.x + b1v.x;
    xnc.y = (c0.y - muc) * ivc * w1v.y + b1v.y;
    xnc.z = (c0.z - muc) * ivc * w1v.z + b1v.z;
    xnc.w = (c0.w - muc) * ivc * w1v.w + b1v.w;
    if (hp) {
        xnp.x = (p0.x - mup) * ivp * w1v.x + b1v.x;
        xnp.y = (p0.y - mup) * ivp * w1v.y + b1v.y;
        xnp.z = (p0.z - mup) * ivp * w1v.z + b1v.z;
        xnp.w = (p0.w - mup) * ivp * w1v.w + b1v.w;
    } else {
        xnp = make_float4(0.f, 0.f, 0.f, 0.f);
    }
    float4 dd = make_float4(xnc.x - xnp.x, xnc.y - xnp.y,
                            xnc.z - xnp.z, xnc.w - xnp.w);
    size_t idx = (size_t)m * (Cv / 4) + tid;

#define DO_MIX(TM, OUT) { \
    float4 w = ((const float4*)TM)[tid]; \
    float4 o; \
    o.x = fmaf(dd.x, w.x, xnp.x); o.y = fmaf(dd.y, w.y, xnp.y); \
    o.z = fmaf(dd.z, w.z, xnp.z); o.w = fmaf(dd.w, w.w, xnp.w); \
    st_half4(OUT, idx, o); }

    DO_MIX(tmk, xk)
    DO_MIX(tmv, xv)
    DO_MIX(tmr, xr)
    DO_MIX(tmg, xg)
#undef DO_MIX
}

// ---------------------------------------------------------------------------
// Fused LN2+token-shift-mix2 -> half outputs (r8 block-per-token version)
// ---------------------------------------------------------------------------
__global__ __launch_bounds__(256) void ln2mix2_kernel(
    const float* __restrict__ in,
    const float* __restrict__ w2, const float* __restrict__ b2,
    const float* __restrict__ tmk, const float* __restrict__ tmr,
    __half* __restrict__ xk, __half* __restrict__ xr)
{
    __shared__ float shm[32];
    int m = blockIdx.x, tid = threadIdx.x;
    bool hp = (m % Tv) != 0;

    const float4 vc = ((const float4*)(in + (size_t)m * Cv))[tid];
    float4 vp = make_float4(0.f, 0.f, 0.f, 0.f);
    if (hp) vp = ((const float4*)(in + (size_t)(m - 1) * Cv))[tid];

    float4 r0 = block_reduce4(
        vc.x + vc.y + vc.z + vc.w,
        vc.x*vc.x + vc.y*vc.y + vc.z*vc.z + vc.w*vc.w,
        vp.x + vp.y + vp.z + vp.w,
        vp.x*vp.x + vp.y*vp.y + vp.z*vp.z + vp.w*vp.w, shm);

    float muc = r0.x * (1.0f / Cv);
    float ivc = rsqrtf(r0.y * (1.0f / Cv) - muc * muc + EPSv);
    float mup = r0.z * (1.0f / Cv);
    float ivp = rsqrtf(r0.w * (1.0f / Cv) - mup * mup + EPSv);

    const float4 wv = ((const float4*)w2)[tid];
    const float4 bv = ((const float4*)b2)[tid];
    float4 xnc, xnp;
    xnc.x = (vc.x - muc) * ivc * wv.x + bv.x;
    xnc.y = (vc.y - muc) * ivc * wv.y + bv.y;
    xnc.z = (vc.z - muc) * ivc * wv.z + bv.z;
    xnc.w = (vc.w - muc) * ivc * wv.w + bv.w;
    if (hp) {
        xnp.x = (vp.x - mup) * ivp * wv.x + bv.x;
        xnp.y = (vp.y - mup) * ivp * wv.y + bv.y;
        xnp.z = (vp.z - mup) * ivp * wv.z + bv.z;
        xnp.w = (vp.w - mup) * ivp * wv.w + bv.w;
    } else {
        xnp = make_float4(0.f, 0.f, 0.f, 0.f);
    }
    float4 dd = make_float4(xnc.x - xnp.x, xnc.y - xnp.y,
                            xnc.z - xnp.z, xnc.w - xnp.w);
    size_t idx = (size_t)m * (Cv / 4) + tid;

#define DO_MIX(TM, OUT) { \
    float4 w = ((const float4*)TM)[tid]; \
    float4 o; \
    o.x = fmaf(dd.x, w.x, xnp.x); o.y = fmaf(dd.y, w.y, xnp.y); \
    o.z = fmaf(dd.z, w.z, xnp.z); o.w = fmaf(dd.w, w.w, xnp.w); \
    st_half4(OUT, idx, o); }

    DO_MIX(tmk, xk)
    DO_MIX(tmr, xr)
#undef DO_MIX
}

// ---------------------------------------------------------------------------
// FP16 tensor-core NT GEMM core (r8 proven mainloop).
// EP: 4 +res(f32 out), 5 C(f32) += mul(half)*acc,
//     6 runtime {0 none->f32, 1 silu->f32, 2 relu^2->half, 3 sigmoid->half,
//                4 silu->half, 5 none->half}
// ---------------------------------------------------------------------------
template<int EP>
__device__ __forceinline__ void gemm_core(
    const __half* __restrict__ A, const __half* __restrict__ B,
    void* __restrict__ Cp, int M, int N, int K,
    const float* __restrict__ res, const __half* __restrict__ mulh,
    int rt_ep, __half* smem, int bm, int bn)
{
    const int BM = 128, BN = 256, BK = 64, P = 72;
    __half* As = smem;
    __half* Bs = smem + 3 * BM * P;

    const int tid  = threadIdx.x;
    const int wid  = tid >> 5;
    const int lane = tid & 31;
    const int warp_m = (wid & 1) * 64;
    const int warp_n = (wid >> 1) * 64;
    const int gr = lane >> 2;
    const int gc = lane & 3;

    const __half* Abase = A + (size_t)bm * K;
    const __half* Bbase = B + (size_t)bn * K;

    const unsigned asmem = (unsigned)__cvta_generic_to_shared(As);
    const unsigned bsmem = (unsigned)__cvta_generic_to_shared(Bs);
    const unsigned aoff = asmem + (unsigned)(((warp_m + (lane & 15)) * P + ((lane & 16) >> 1)) * 2);
    const unsigned boff = bsmem + (unsigned)(((warp_n + (lane & 7) + ((lane & 16) >> 1)) * P + (lane & 8)) * 2);
    const unsigned BUFA = BM * P * 2;
    const unsigned BUFB = BN * P * 2;
    const unsigned R16  = 16 * P * 2;

    const int arow = tid >> 3;
    const int aseg = tid & 7;

#define PREFETCH(kt, buf) { \
    int k0 = (kt) * BK; \
    _Pragma("unroll") \
    for (int c = 0; c < 4; c++) { \
        int row = arow + c * 32; \
        cp_async16(As + (buf) * BM * P + row * P + aseg * 8, \
                   Abase + (size_t)row * K + k0 + aseg * 8); \
    } \
    _Pragma("unroll") \
    for (int c = 0; c < 8; c++) { \
        int row = arow + c * 32; \
        cp_async16(Bs + (buf) * BN * P + row * P + aseg * 8, \
                   Bbase + (size_t)row * K + k0 + aseg * 8); \
    } \
    CP_COMMIT(); }

    float acc[4][8][4];
#pragma unroll
    for (int mt = 0; mt < 4; mt++)
#pragma unroll
        for (int nt = 0; nt < 8; nt++)
#pragma unroll
            for (int q = 0; q < 4; q++) acc[mt][nt][q] = 0.f;

    const int NT = K / BK;
    PREFETCH(0, 0)
    PREFETCH(1, 1)

    int buf = 0;
    for (int kt = 0; kt < NT; kt++) {
        if (kt + 1 < NT) { CP_WAIT1(); } else { CP_WAIT0(); }
        __syncthreads();
        int nbuf = buf + 2; if (nbuf >= 3) nbuf -= 3;
        if (kt + 2 < NT) PREFETCH(kt + 2, nbuf)

        const unsigned ab = aoff + buf * BUFA;
        const unsigned bb = boff + buf * BUFB;
#pragma unroll
        for (int kk = 0; kk < BK; kk += 16) {
            uint32_t af[4][4], bf[8][2];
#pragma unroll
            for (int mt = 0; mt < 4; mt++)
                LDSM4(af[mt][0], af[mt][1], af[mt][2], af[mt][3],
                      ab + mt * R16 + kk * 2);
#pragma unroll
            for (int p = 0; p < 4; p++)
                LDSM4(bf[2*p][0], bf[2*p][1], bf[2*p+1][0], bf[2*p+1][1],
                      bb + p * R16 + kk * 2);
#pragma unroll
            for (int mt = 0; mt < 4; mt++)
#pragma unroll
                for (int nt = 0; nt < 8; nt++) {
                    asm volatile(
                        "mma.sync.aligned.m16n8k16.row.col.f32.f16.f16.f32 "
                        "{%0,%1,%2,%3}, {%4,%5,%6,%7}, {%8,%9}, {%0,%1,%2,%3};"
                        : "+f"(acc[mt][nt][0]), "+f"(acc[mt][nt][1]),
                          "+f"(acc[mt][nt][2]), "+f"(acc[mt][nt][3])
                        : "r"(af[mt][0]), "r"(af[mt][1]), "r"(af[mt][2]), "r"(af[mt][3]),
                          "r"(bf[nt][0]), "r"(bf[nt][1]));
                }
        }
        buf = buf + 1; if (buf >= 3) buf -= 3;
    }
#undef PREFETCH

    float* Cf = (float*)Cp;
    __half* Ch = (__half*)Cp;
#pragma unroll
    for (int mt = 0; mt < 4; mt++) {
#pragma unroll
        for (int nt = 0; nt < 8; nt++) {
            int row = bm + warp_m + mt * 16 + gr;
            int col = bn + warp_n + nt * 8 + 2 * gc;
#pragma unroll
            for (int half_ = 0; half_ < 2; half_++) {
                size_t idx = (size_t)(row + half_ * 8) * N + col;
                float a0 = acc[mt][nt][half_ * 2 + 0];
                float a1 = acc[mt][nt][half_ * 2 + 1];
                if (EP == 4) {
                    float2 rr = *(const float2*)(res + idx);
                    *(float2*)(Cf + idx) = make_float2(a0 + rr.x, a1 + rr.y);
                } else if (EP == 5) {
                    float2 cc = *(const float2*)(Cf + idx);
                    __half2 mh = *(const __half2*)(mulh + idx);
                    *(float2*)(Cf + idx) = make_float2(
                        cc.x + __low2float(mh) * a0,
                        cc.y + __high2float(mh) * a1);
                } else { // EP == 6 runtime
                    if (rt_ep == 2) {          // relu^2 -> half
                        float z0 = fmaxf(a0, 0.f), z1 = fmaxf(a1, 0.f);
                        *(__half2*)(Ch + idx) = __floats2half2_rn(z0 * z0, z1 * z1);
                    } else if (rt_ep == 3) {   // sigmoid -> half
                        float s0 = 1.f / (1.f + expf(-a0));
                        float s1 = 1.f / (1.f + expf(-a1));
                        *(__half2*)(Ch + idx) = __floats2half2_rn(s0, s1);
                    } else if (rt_ep == 4) {   // silu -> half
                        float s0 = a0 / (1.f + expf(-a0));
                        float s1 = a1 / (1.f + expf(-a1));
                        *(__half2*)(Ch + idx) = __floats2half2_rn(s0, s1);
                    } else if (rt_ep == 5) {   // none -> half
                        *(__half2*)(Ch + idx) = __floats2half2_rn(a0, a1);
                    } else if (rt_ep == 1) {   // silu -> f32
                        *(float2*)(Cf + idx) = make_float2(a0 / (1.f + expf(-a0)),
                                                           a1 / (1.f + expf(-a1)));
                    } else {                   // none -> f32
                        *(float2*)(Cf + idx) = make_float2(a0, a1);
                    }
                }
            }
        }
    }
}

template<int EP>
__global__ __launch_bounds__(256, 1) void gemm_f16(
    const __half* __restrict__ A, const __half* __restrict__ B,
    void* __restrict__ C, int M, int N, int K,
    const float* __restrict__ res, const __half* __restrict__ mulh)
{
    extern __shared__ __half smem[];
    gemm_core<EP>(A, B, C, M, N, K, res, mulh, 0, smem,
                  blockIdx.y * 128, blockIdx.x * 256);
}

// 4 projection GEMMs in one launch; z in {0,1,2} plain->half, z==3 silu->half
__global__ __launch_bounds__(256, 1) void gemm_proj4(
    const __half* __restrict__ A0, const __half* __restrict__ A1,
    const __half* __restrict__ A2, const __half* __restrict__ A3,
    const __half* __restrict__ B0, const __half* __restrict__ B1,
    const __half* __restrict__ B2, const __half* __restrict__ B3,
    __half* __restrict__ C0, __half* __restrict__ C1,
    __half* __restrict__ C2, __half* __restrict__ C3)
{
    extern __shared__ __half smem[];
    const __half* A; const __half* Bw; __half* C; int ep;
    int z = blockIdx.z;
    if (z == 0)      { A = A0; Bw = B0; C = C0; ep = 5; }
    else if (z == 1) { A = A1; Bw = B1; C = C1; ep = 5; }
    else if (z == 2) { A = A2; Bw = B2; C = C2; ep = 5; }
    else             { A = A3; Bw = B3; C = C3; ep = 4; }
    gemm_core<6>(A, Bw, C, Mv, Cv, Cv, nullptr, nullptr, ep,
                 smem, blockIdx.y * 128, blockIdx.x * 256);
}

// FFN-K (relu^2 -> half, N=3584) + FFN-R (sigmoid -> half, N=1024)
__global__ __launch_bounds__(256, 1) void gemm_ffnpair(
    const __half* __restrict__ Ak, const __half* __restrict__ Bk, __half* __restrict__ Ck,
    const __half* __restrict__ Ar, const __half* __restrict__ Br, __half* __restrict__ Cr)
{
    extern __shared__ __half smem[];
    const int TK = FFNv / 256;
    if ((int)blockIdx.x < TK)
        gemm_core<6>(Ak, Bk, Ck, Mv, FFNv, Cv, nullptr, nullptr, 2,
                     smem, blockIdx.y * 128, blockIdx.x * 256);
    else
        gemm_core<6>(Ar, Br, Cr, Mv, Cv, Cv, nullptr, nullptr, 3,
                     smem, blockIdx.y * 128, (blockIdx.x - TK) * 256);
}

// ---------------------------------------------------------------------------
// WKV5 recurrence, half inputs, fp32 state, CH=16
// ---------------------------------------------------------------------------
__global__ __launch_bounds__(256) void wkv_kernel(
    const __half* __restrict__ r, const __half* __restrict__ k,
    const __half* __restrict__ v,
    const float* __restrict__ decay, const float* __restrict__ faaaa,
    float* __restrict__ y)
{
    const int CH = 16;
    __shared__ float sr[CH][Nv], sk[CH][Nv], sv[CH][Nv];

    int bh = blockIdx.x;
    int b = bh / Hv, h = bh % Hv;
    int tid = threadIdx.x;
    int j  = tid >> 2;
    int gq = tid & 3;
    int ib = gq * 16;

    float S[16], ew[16], uu[16];
#pragma unroll
    for (int ii = 0; ii < 16; ii++) {
        S[ii]  = 0.f;
        ew[ii] = expf(-expf(decay[h * Nv + ib + ii]));
        uu[ii] = faaaa[h * Nv + ib + ii];
    }

    size_t base = ((size_t)b * Tv) * Cv + (size_t)h * Nv;

    for (int tc = 0; tc < Tv; tc += CH) {
        __syncthreads();
        // stage CH x 64 halves per tensor via uint2 (4 halves) loads
        for (int idx = tid; idx < CH * 16; idx += 256) {
            int st = idx >> 4, c4 = idx & 15;
            size_t off = base + (size_t)(tc + st) * Cv + c4 * 4;
#define LD4H(SRC, DST) { \
            uint2 u = *(const uint2*)(SRC + off); \
            __half2 h01 = *reinterpret_cast<__half2*>(&u.x); \
            __half2 h23 = *reinterpret_cast<__half2*>(&u.y); \
            DST[st][c4*4+0] = __low2float(h01);  DST[st][c4*4+1] = __high2float(h01); \
            DST[st][c4*4+2] = __low2float(h23);  DST[st][c4*4+3] = __high2float(h23); }
            LD4H(r, sr)
            LD4H(k, sk)
            LD4H(v, sv)
#undef LD4H
        }
        __syncthreads();

#pragma unroll
        for (int st = 0; st < CH; st++) {
            float vj = sv[st][j];
            float y0 = 0.f;
#pragma unroll
            for (int ii = 0; ii < 16; ii++) {
                float ri = sr[st][ib + ii];
                float ki = sk[st][ib + ii];
                float t = ki * vj;
                y0 = fmaf(ri, fmaf(uu[ii], t, S[ii]), y0);
                S[ii] = fmaf(ew[ii], S[ii], t);
            }
            y0 += __shfl_xor_sync(0xffffffffu, y0, 1);
            y0 += __shfl_xor_sync(0xffffffffu, y0, 2);
            if (gq == 0)
                y[base + (size_t)(tc + st) * Cv + j] = y0;
        }
    }
}

// ---------------------------------------------------------------------------
// GroupNorm * gate(half) -> half output
// ---------------------------------------------------------------------------
__global__ __launch_bounds__(256) void gnmul_kernel(
    const float* __restrict__ y, const __half* __restrict__ g,
    const float* __restrict__ w, const float* __restrict__ b,
    __half* __restrict__ ym)
{
    int m = blockIdx.x, tid = threadIdx.x;
    size_t base = (size_t)m * Cv;
    float4 v = ((const float4*)(y + base))[tid];
    const float s8 = 1.0f / 8.0f;
    v.x *= s8; v.y *= s8; v.z *= s8; v.w *= s8;

    float s  = v.x + v.y + v.z + v.w;
    float ss = v.x*v.x + v.y*v.y + v.z*v.z + v.w*v.w;
#pragma unroll
    for (int o = 8; o; o >>= 1) {
        s  += __shfl_xor_sync(0xffffffffu, s,  o);
        ss += __shfl_xor_sync(0xffffffffu, ss, o);
    }
    float mu  = s * (1.0f / Nv);
    float var = ss * (1.0f / Nv) - mu * mu;
    float inv = rsqrtf(var + EPSv);

    float4 wv = ((const float4*)w)[tid];
    float4 bv = ((const float4*)b)[tid];
    uint2 gu = *(const uint2*)(g + base + (size_t)tid * 4);
    __half2 g01 = *reinterpret_cast<__half2*>(&gu.x);
    __half2 g23 = *reinterpret_cast<__half2*>(&gu.y);
    float4 gv = make_float4(__low2float(g01), __high2float(g01),
                            __low2float(g23), __high2float(g23));
    float4 o;
    o.x = ((v.x - mu) * inv * wv.x + bv.x) * gv.x;
    o.y = ((v.y - mu) * inv * wv.y + bv.y) * gv.y;
    o.z = ((v.z - mu) * inv * wv.z + bv.z) * gv.z;
    o.w = ((v.w - mu) * inv * wv.w + bv.w) * gv.w;
    st_half4(ym, base / 4 + tid, o);
}

// ---------------------------------------------------------------------------
// launch
// ---------------------------------------------------------------------------
#define GEMM_SMEM (3 * (128 * 72 + 256 * 72) * 2)   /* 165,888 B */

extern "C" void kernel_launch(void* const* d_in, const int* in_sizes, int n_in,
                              void* d_out, int out_size)
{
    const float* x        = (const float*)d_in[0];
    const float* ln0_w    = (const float*)d_in[1];
    const float* ln0_b    = (const float*)d_in[2];
    const float* ln1_w    = (const float*)d_in[3];
    const float* ln1_b    = (const float*)d_in[4];
    const float* ln2_w    = (const float*)d_in[5];
    const float* ln2_b    = (const float*)d_in[6];
    const float* att_tmk  = (const float*)d_in[7];
    const float* att_tmv  = (const float*)d_in[8];
    const float* att_tmr  = (const float*)d_in[9];
    const float* att_tmg  = (const float*)d_in[10];
    const float* att_decay  = (const float*)d_in[11];
    const float* att_faaaa  = (const float*)d_in[12];
    const float* att_Wr   = (const float*)d_in[13];
    const float* att_Wk   = (const float*)d_in[14];
    const float* att_Wv   = (const float*)d_in[15];
    const float* att_Wg   = (const float*)d_in[16];
    const float* att_Wo   = (const float*)d_in[17];
    const float* att_lnx_w = (const float*)d_in[18];
    const float* att_lnx_b = (const float*)d_in[19];
    const float* ffn_tmk  = (const float*)d_in[20];
    const float* ffn_tmr  = (const float*)d_in[21];
    const float* ffn_Wk   = (const float*)d_in[22];
    const float* ffn_Wr   = (const float*)d_in[23];
    const float* ffn_Wv   = (const float*)d_in[24];
    float* out = (float*)d_out;

    void* poolv = nullptr;
    cudaGetSymbolAddress(&poolv, g_pool);
    float* pool = (float*)poolv;

    float*  bx0  = pool + OFF_X0;
    __half* bxr  = (__half*)(pool + OFF_XR);
    __half* bxk  = (__half*)(pool + OFF_XK);
    __half* bxv  = (__half*)(pool + OFF_XV);
    __half* bxg  = (__half*)(pool + OFF_XG);
    __half* br   = (__half*)(pool + OFF_R);
    __half* bk   = (__half*)(pool + OFF_K);
    __half* bv   = (__half*)(pool + OFF_V);
    __half* bg   = (__half*)(pool + OFF_G);
    float*  by   = pool + OFF_Y;
    __half* bym  = (__half*)(pool + OFF_YM);
    __half* bxk2 = (__half*)(pool + OFF_XK2);
    __half* bxr2 = (__half*)(pool + OFF_XR2);
    __half* bsr  = (__half*)(pool + OFF_SR);
    __half* bkf  = (__half*)(pool + OFF_KF);
    __half* wWr  = (__half*)(pool + OFF_WR);
    __half* wWk  = (__half*)(pool + OFF_WK);
    __half* wWv  = (__half*)(pool + OFF_WV);
    __half* wWg  = (__half*)(pool + OFF_WG);
    __half* wWo  = (__half*)(pool + OFF_WO);
    __half* wFWr = (__half*)(pool + OFF_FWR);
    __half* wFWk = (__half*)(pool + OFF_FWK);
    __half* wFWv = (__half*)(pool + OFF_FWV);

    cudaFuncSetAttribute(gemm_f16<4>,  cudaFuncAttributeMaxDynamicSharedMemorySize, GEMM_SMEM);
    cudaFuncSetAttribute(gemm_f16<5>,  cudaFuncAttributeMaxDynamicSharedMemorySize, GEMM_SMEM);
    cudaFuncSetAttribute(gemm_proj4,   cudaFuncAttributeMaxDynamicSharedMemorySize, GEMM_SMEM);
    cudaFuncSetAttribute(gemm_ffnpair, cudaFuncAttributeMaxDynamicSharedMemorySize, GEMM_SMEM);

    // all weight conversions in one launch
    const int nCC4 = (int)(WCC / 4), nFC4 = (int)(WFC / 4);
    dim3 gW((nFC4 + 255) / 256, 1, 8);
    cvtw_all_kernel<<<gW, 256>>>(att_Wr, att_Wk, att_Wv, att_Wg, att_Wo, ffn_Wr,
                                 ffn_Wk, ffn_Wv,
                                 wWr, wWk, wWv, wWg, wWo, wFWr, wFWk, wFWv,
                                 nCC4, nFC4);

    // attention path
    ln01mix4_kernel<<<Mv, 256>>>(x, ln0_w, ln0_b, ln1_w, ln1_b,
                                 att_tmk, att_tmv, att_tmr, att_tmg,
                                 bx0, bxk, bxv, bxr, bxg);
    dim3 gP(Cv / 256, Mv / 128, 4);
    gemm_proj4<<<gP, 256, GEMM_SMEM>>>(bxr, bxk, bxv, bxg,
                                       wWr, wWk, wWv, wWg,
                                       br, bk, bv, bg);
    wkv_kernel<<<Bv * Hv, 256>>>(br, bk, bv, att_decay, att_faaaa, by);
    gnmul_kernel<<<Mv, 256>>>(by, bg, att_lnx_w, att_lnx_b, bym);
    dim3 gC(Cv / 256, Mv / 128);
    gemm_f16<4><<<gC, 256, GEMM_SMEM>>>(bym, wWo, out, Mv, Cv, Cv, bx0, nullptr);

    // channel-mix path
    ln2mix2_kernel<<<Mv, 256>>>(out, ln2_w, ln2_b, ffn_tmk, ffn_tmr, bxk2, bxr2);
    dim3 gPair(FFNv / 256 + Cv / 256, Mv / 128);
    gemm_ffnpair<<<gPair, 256, GEMM_SMEM>>>(bxk2, wFWk, bkf, bxr2, wFWr, bsr);
    gemm_f16<5><<<gC, 256, GEMM_SMEM>>>(bkf, wFWv, out, Mv, Cv, FFNv, nullptr, bsr);
}

// round 14
// speedup vs baseline: 1.4078x; 1.4078x over previous
#include <cuda_runtime.h>
#include <cuda_fp16.h>
#include <cstdint>
#include <math.h>

#define Bv   8
#define Tv   2048
#define Cv   1024
#define Hv   16
#define Nv   64
#define FFNv 3584
#define Mv   (Bv*Tv)          /* 16384 tokens */
#define EPSv 1e-5f

// ---------------------------------------------------------------------------
// Scratch pool
// ---------------------------------------------------------------------------
#define MC   ((size_t)Mv * Cv)
#define MF   ((size_t)Mv * FFNv)
#define WCC  ((size_t)Cv * Cv)
#define WFC  ((size_t)FFNv * Cv)
__device__ float g_pool[16 * MC + MF + 6 * WCC + 2 * WFC];

#define OFF_X0   (0*MC)
#define OFF_XR   (2*MC)
#define OFF_XK   (3*MC)
#define OFF_XV   (4*MC)
#define OFF_XG   (5*MC)
#define OFF_R    (6*MC)
#define OFF_K    (7*MC)
#define OFF_V    (8*MC)
#define OFF_G    (9*MC)
#define OFF_Y    (10*MC)
#define OFF_YM   (11*MC)
#define OFF_XK2  (13*MC)
#define OFF_XR2  (14*MC)
#define OFF_SR   (15*MC)
#define OFF_KF   (16*MC)
#define OFF_W    (16*MC + MF)
#define OFF_WR   (OFF_W + 0*WCC)
#define OFF_WK   (OFF_W + 1*WCC)
#define OFF_WV   (OFF_W + 2*WCC)
#define OFF_WG   (OFF_W + 3*WCC)
#define OFF_WO   (OFF_W + 4*WCC)
#define OFF_FWR  (OFF_W + 5*WCC)
#define OFF_FWK  (OFF_W + 6*WCC)
#define OFF_FWV  (OFF_W + 6*WCC + WFC)

// ---------------------------------------------------------------------------
// helpers
// ---------------------------------------------------------------------------
__device__ __forceinline__ float4 block_reduce4(float a, float b, float c, float d,
                                                float* shm /*32*/)
{
#pragma unroll
    for (int o = 16; o; o >>= 1) {
        a += __shfl_xor_sync(0xffffffffu, a, o);
        b += __shfl_xor_sync(0xffffffffu, b, o);
        c += __shfl_xor_sync(0xffffffffu, c, o);
        d += __shfl_xor_sync(0xffffffffu, d, o);
    }
    int w = threadIdx.x >> 5;
    if ((threadIdx.x & 31) == 0) { shm[w] = a; shm[8+w] = b; shm[16+w] = c; shm[24+w] = d; }
    __syncthreads();
    a = shm[0]; b = shm[8]; c = shm[16]; d = shm[24];
#pragma unroll
    for (int i = 1; i < 8; i++) {
        a += shm[i]; b += shm[8+i]; c += shm[16+i]; d += shm[24+i];
    }
    return make_float4(a, b, c, d);
}

__device__ __forceinline__ void st_half4(__half* p, size_t i4, float4 v)
{
    __half2 lo = __floats2half2_rn(v.x, v.y);
    __half2 hi = __floats2half2_rn(v.z, v.w);
    uint2 u;
    u.x = *reinterpret_cast<unsigned*>(&lo);
    u.y = *reinterpret_cast<unsigned*>(&hi);
    *reinterpret_cast<uint2*>(p + i4 * 4) = u;
}

__device__ __forceinline__ void cp_async16(void* smem, const void* gptr)
{
    unsigned saddr = (unsigned)__cvta_generic_to_shared(smem);
    asm volatile("cp.async.ca.shared.global [%0], [%1], 16;\n" :: "r"(saddr), "l"(gptr));
}
#define CP_COMMIT() asm volatile("cp.async.commit_group;\n" ::: "memory")
#define CP_WAIT0()  asm volatile("cp.async.wait_group 0;\n" ::: "memory")
#define CP_WAIT1()  asm volatile("cp.async.wait_group 1;\n" ::: "memory")

#define LDSM4(r0, r1, r2, r3, addr) \
    asm volatile("ldmatrix.sync.aligned.m8n8.x4.shared.b16 {%0,%1,%2,%3}, [%4];" \
                 : "=r"(r0), "=r"(r1), "=r"(r2), "=r"(r3) : "r"(addr))

// ---------------------------------------------------------------------------
// all weights fp32 -> fp16 in one launch (grid.z selects tensor)
// ---------------------------------------------------------------------------
__global__ __launch_bounds__(256) void cvtw_all_kernel(
    const float* __restrict__ i0, const float* __restrict__ i1,
    const float* __restrict__ i2, const float* __restrict__ i3,
    const float* __restrict__ i4, const float* __restrict__ i5,
    const float* __restrict__ i6, const float* __restrict__ i7,
    __half* __restrict__ o0, __half* __restrict__ o1,
    __half* __restrict__ o2, __half* __restrict__ o3,
    __half* __restrict__ o4, __half* __restrict__ o5,
    __half* __restrict__ o6, __half* __restrict__ o7,
    int nCC4, int nFC4)
{
    int z = blockIdx.z;
    const float* in; __half* outp; int n4;
    switch (z) {
        case 0: in = i0; outp = o0; n4 = nCC4; break;
        case 1: in = i1; outp = o1; n4 = nCC4; break;
        case 2: in = i2; outp = o2; n4 = nCC4; break;
        case 3: in = i3; outp = o3; n4 = nCC4; break;
        case 4: in = i4; outp = o4; n4 = nCC4; break;
        case 5: in = i5; outp = o5; n4 = nCC4; break;
        case 6: in = i6; outp = o6; n4 = nFC4; break;
        default: in = i7; outp = o7; n4 = nFC4; break;
    }
    int idx = blockIdx.x * blockDim.x + threadIdx.x;
    if (idx >= n4) return;
    float4 v = ((const float4*)in)[idx];
    st_half4(outp, idx, v);
}

// ---------------------------------------------------------------------------
// Fused LN0+LN1+token-shift-mix4 -> half outputs (r8 block-per-token)
// ---------------------------------------------------------------------------
__global__ __launch_bounds__(256) void ln01mix4_kernel(
    const float* __restrict__ x,
    const float* __restrict__ w0, const float* __restrict__ b0,
    const float* __restrict__ w1, const float* __restrict__ b1,
    const float* __restrict__ tmk, const float* __restrict__ tmv,
    const float* __restrict__ tmr, const float* __restrict__ tmg,
    float* __restrict__ x0,
    __half* __restrict__ xk, __half* __restrict__ xv,
    __half* __restrict__ xr, __half* __restrict__ xg)
{
    __shared__ float shm1[32], shm2[32];
    int m = blockIdx.x, tid = threadIdx.x;
    bool hp = (m % Tv) != 0;

    const float4 vc = ((const float4*)(x + (size_t)m * Cv))[tid];
    float4 vp = make_float4(0.f, 0.f, 0.f, 0.f);
    if (hp) vp = ((const float4*)(x + (size_t)(m - 1) * Cv))[tid];

    float4 r0 = block_reduce4(
        vc.x + vc.y + vc.z + vc.w,
        vc.x*vc.x + vc.y*vc.y + vc.z*vc.z + vc.w*vc.w,
        vp.x + vp.y + vp.z + vp.w,
        vp.x*vp.x + vp.y*vp.y + vp.z*vp.z + vp.w*vp.w, shm1);

    float muc = r0.x * (1.0f / Cv);
    float ivc = rsqrtf(r0.y * (1.0f / Cv) - muc * muc + EPSv);
    float mup = r0.z * (1.0f / Cv);
    float ivp = rsqrtf(r0.w * (1.0f / Cv) - mup * mup + EPSv);

    const float4 w0v = ((const float4*)w0)[tid];
    const float4 b0v = ((const float4*)b0)[tid];
    float4 c0, p0;
    c0.x = (vc.x - muc) * ivc * w0v.x + b0v.x;
    c0.y = (vc.y - muc) * ivc * w0v.y + b0v.y;
    c0.z = (vc.z - muc) * ivc * w0v.z + b0v.z;
    c0.w = (vc.w - muc) * ivc * w0v.w + b0v.w;
    p0.x = (vp.x - mup) * ivp * w0v.x + b0v.x;
    p0.y = (vp.y - mup) * ivp * w0v.y + b0v.y;
    p0.z = (vp.z - mup) * ivp * w0v.z + b0v.z;
    p0.w = (vp.w - mup) * ivp * w0v.w + b0v.w;
    ((float4*)(x0 + (size_t)m * Cv))[tid] = c0;

    float4 r1 = block_reduce4(
        c0.x + c0.y + c0.z + c0.w,
        c0.x*c0.x + c0.y*c0.y + c0.z*c0.z + c0.w*c0.w,
        p0.x + p0.y + p0.z + p0.w,
        p0.x*p0.x + p0.y*p0.y + p0.z*p0.z + p0.w*p0.w, shm2);

    muc = r1.x * (1.0f / Cv);
    ivc = rsqrtf(r1.y * (1.0f / Cv) - muc * muc + EPSv);
    mup = r1.z * (1.0f / Cv);
    ivp = rsqrtf(r1.w * (1.0f / Cv) - mup * mup + EPSv);

    const float4 w1v = ((const float4*)w1)[tid];
    const float4 b1v = ((const float4*)b1)[tid];
    float4 xnc, xnp;
    xnc.x = (c0.x - muc) * ivc * w1v.x + b1v.x;
    xnc.y = (c0.y - muc) * ivc * w1v.y + b1v.y;
    xnc.z = (c0.z - muc) * ivc * w1v.z + b1v.z;
    xnc.w = (c0.w - muc) * ivc * w1v.w + b1v.w;
    if (hp) {
        xnp.x = (p0.x - mup) * ivp * w1v.x + b1v.x;
        xnp.y = (p0.y - mup) * ivp * w1v.y + b1v.y;
        xnp.z = (p0.z - mup) * ivp * w1v.z + b1v.z;
        xnp.w = (p0.w - mup) * ivp * w1v.w + b1v.w;
    } else {
        xnp = make_float4(0.f, 0.f, 0.f, 0.f);
    }
    float4 dd = make_float4(xnc.x - xnp.x, xnc.y - xnp.y,
                            xnc.z - xnp.z, xnc.w - xnp.w);
    size_t idx = (size_t)m * (Cv / 4) + tid;

#define DO_MIX(TM, OUT) { \
    float4 w = ((const float4*)TM)[tid]; \
    float4 o; \
    o.x = fmaf(dd.x, w.x, xnp.x); o.y = fmaf(dd.y, w.y, xnp.y); \
    o.z = fmaf(dd.z, w.z, xnp.z); o.w = fmaf(dd.w, w.w, xnp.w); \
    st_half4(OUT, idx, o); }

    DO_MIX(tmk, xk)
    DO_MIX(tmv, xv)
    DO_MIX(tmr, xr)
    DO_MIX(tmg, xg)
#undef DO_MIX
}

// ---------------------------------------------------------------------------
// Fused LN2+token-shift-mix2 -> half outputs (r8 block-per-token)
// ---------------------------------------------------------------------------
__global__ __launch_bounds__(256) void ln2mix2_kernel(
    const float* __restrict__ in,
    const float* __restrict__ w2, const float* __restrict__ b2,
    const float* __restrict__ tmk, const float* __restrict__ tmr,
    __half* __restrict__ xk, __half* __restrict__ xr)
{
    __shared__ float shm[32];
    int m = blockIdx.x, tid = threadIdx.x;
    bool hp = (m % Tv) != 0;

    const float4 vc = ((const float4*)(in + (size_t)m * Cv))[tid];
    float4 vp = make_float4(0.f, 0.f, 0.f, 0.f);
    if (hp) vp = ((const float4*)(in + (size_t)(m - 1) * Cv))[tid];

    float4 r0 = block_reduce4(
        vc.x + vc.y + vc.z + vc.w,
        vc.x*vc.x + vc.y*vc.y + vc.z*vc.z + vc.w*vc.w,
        vp.x + vp.y + vp.z + vp.w,
        vp.x*vp.x + vp.y*vp.y + vp.z*vp.z + vp.w*vp.w, shm);

    float muc = r0.x * (1.0f / Cv);
    float ivc = rsqrtf(r0.y * (1.0f / Cv) - muc * muc + EPSv);
    float mup = r0.z * (1.0f / Cv);
    float ivp = rsqrtf(r0.w * (1.0f / Cv) - mup * mup + EPSv);

    const float4 wv = ((const float4*)w2)[tid];
    const float4 bv = ((const float4*)b2)[tid];
    float4 xnc, xnp;
    xnc.x = (vc.x - muc) * ivc * wv.x + bv.x;
    xnc.y = (vc.y - muc) * ivc * wv.y + bv.y;
    xnc.z = (vc.z - muc) * ivc * wv.z + bv.z;
    xnc.w = (vc.w - muc) * ivc * wv.w + bv.w;
    if (hp) {
        xnp.x = (vp.x - mup) * ivp * wv.x + bv.x;
        xnp.y = (vp.y - mup) * ivp * wv.y + bv.y;
        xnp.z = (vp.z - mup) * ivp * wv.z + bv.z;
        xnp.w = (vp.w - mup) * ivp * wv.w + bv.w;
    } else {
        xnp = make_float4(0.f, 0.f, 0.f, 0.f);
    }
    float4 dd = make_float4(xnc.x - xnp.x, xnc.y - xnp.y,
                            xnc.z - xnp.z, xnc.w - xnp.w);
    size_t idx = (size_t)m * (Cv / 4) + tid;

#define DO_MIX(TM, OUT) { \
    float4 w = ((const float4*)TM)[tid]; \
    float4 o; \
    o.x = fmaf(dd.x, w.x, xnp.x); o.y = fmaf(dd.y, w.y, xnp.y); \
    o.z = fmaf(dd.z, w.z, xnp.z); o.w = fmaf(dd.w, w.w, xnp.w); \
    st_half4(OUT, idx, o); }

    DO_MIX(tmk, xk)
    DO_MIX(tmr, xr)
#undef DO_MIX
}

// ---------------------------------------------------------------------------
// FP16 tensor-core NT GEMM core (r8 proven).
// EP: 4 +res(f32 out), 5 C(f32) += mul(f32)*acc,
//     6 runtime {0 none->f32, 1 silu->f32, 2 relu^2->half, 3 sigmoid->f32,
//                4 silu->half}
// ---------------------------------------------------------------------------
template<int EP>
__device__ __forceinline__ void gemm_core(
    const __half* __restrict__ A, const __half* __restrict__ B,
    void* __restrict__ Cp, int M, int N, int K,
    const float* __restrict__ res, const float* __restrict__ mul,
    int rt_ep, __half* smem, int bm, int bn)
{
    const int BM = 128, BN = 256, BK = 64, P = 72;
    __half* As = smem;
    __half* Bs = smem + 3 * BM * P;

    const int tid  = threadIdx.x;
    const int wid  = tid >> 5;
    const int lane = tid & 31;
    const int warp_m = (wid & 1) * 64;
    const int warp_n = (wid >> 1) * 64;
    const int gr = lane >> 2;
    const int gc = lane & 3;

    const __half* Abase = A + (size_t)bm * K;
    const __half* Bbase = B + (size_t)bn * K;

    const unsigned asmem = (unsigned)__cvta_generic_to_shared(As);
    const unsigned bsmem = (unsigned)__cvta_generic_to_shared(Bs);
    const unsigned aoff = asmem + (unsigned)(((warp_m + (lane & 15)) * P + ((lane & 16) >> 1)) * 2);
    const unsigned boff = bsmem + (unsigned)(((warp_n + (lane & 7) + ((lane & 16) >> 1)) * P + (lane & 8)) * 2);
    const unsigned BUFA = BM * P * 2;
    const unsigned BUFB = BN * P * 2;
    const unsigned R16  = 16 * P * 2;

    const int arow = tid >> 3;
    const int aseg = tid & 7;

#define PREFETCH(kt, buf) { \
    int k0 = (kt) * BK; \
    _Pragma("unroll") \
    for (int c = 0; c < 4; c++) { \
        int row = arow + c * 32; \
        cp_async16(As + (buf) * BM * P + row * P + aseg * 8, \
                   Abase + (size_t)row * K + k0 + aseg * 8); \
    } \
    _Pragma("unroll") \
    for (int c = 0; c < 8; c++) { \
        int row = arow + c * 32; \
        cp_async16(Bs + (buf) * BN * P + row * P + aseg * 8, \
                   Bbase + (size_t)row * K + k0 + aseg * 8); \
    } \
    CP_COMMIT(); }

    float acc[4][8][4];
#pragma unroll
    for (int mt = 0; mt < 4; mt++)
#pragma unroll
        for (int nt = 0; nt < 8; nt++)
#pragma unroll
            for (int q = 0; q < 4; q++) acc[mt][nt][q] = 0.f;

    const int NT = K / BK;
    PREFETCH(0, 0)
    PREFETCH(1, 1)

    int buf = 0;
    for (int kt = 0; kt < NT; kt++) {
        if (kt + 1 < NT) { CP_WAIT1(); } else { CP_WAIT0(); }
        __syncthreads();
        int nbuf = buf + 2; if (nbuf >= 3) nbuf -= 3;
        if (kt + 2 < NT) PREFETCH(kt + 2, nbuf)

        const unsigned ab = aoff + buf * BUFA;
        const unsigned bb = boff + buf * BUFB;
#pragma unroll
        for (int kk = 0; kk < BK; kk += 16) {
            uint32_t af[4][4], bf[8][2];
#pragma unroll
            for (int mt = 0; mt < 4; mt++)
                LDSM4(af[mt][0], af[mt][1], af[mt][2], af[mt][3],
                      ab + mt * R16 + kk * 2);
#pragma unroll
            for (int p = 0; p < 4; p++)
                LDSM4(bf[2*p][0], bf[2*p][1], bf[2*p+1][0], bf[2*p+1][1],
                      bb + p * R16 + kk * 2);
#pragma unroll
            for (int mt = 0; mt < 4; mt++)
#pragma unroll
                for (int nt = 0; nt < 8; nt++) {
                    asm volatile(
                        "mma.sync.aligned.m16n8k16.row.col.f32.f16.f16.f32 "
                        "{%0,%1,%2,%3}, {%4,%5,%6,%7}, {%8,%9}, {%0,%1,%2,%3};"
                        : "+f"(acc[mt][nt][0]), "+f"(acc[mt][nt][1]),
                          "+f"(acc[mt][nt][2]), "+f"(acc[mt][nt][3])
                        : "r"(af[mt][0]), "r"(af[mt][1]), "r"(af[mt][2]), "r"(af[mt][3]),
                          "r"(bf[nt][0]), "r"(bf[nt][1]));
                }
        }
        buf = buf + 1; if (buf >= 3) buf -= 3;
    }
#undef PREFETCH

    float* Cf = (float*)Cp;
    __half* Ch = (__half*)Cp;
#pragma unroll
    for (int mt = 0; mt < 4; mt++) {
#pragma unroll
        for (int nt = 0; nt < 8; nt++) {
            int row = bm + warp_m + mt * 16 + gr;
            int col = bn + warp_n + nt * 8 + 2 * gc;
#pragma unroll
            for (int half_ = 0; half_ < 2; half_++) {
                size_t idx = (size_t)(row + half_ * 8) * N + col;
                float a0 = acc[mt][nt][half_ * 2 + 0];
                float a1 = acc[mt][nt][half_ * 2 + 1];
                if (EP == 4) {
                    float2 rr = *(const float2*)(res + idx);
                    *(float2*)(Cf + idx) = make_float2(a0 + rr.x, a1 + rr.y);
                } else if (EP == 5) {
                    float2 cc = *(const float2*)(Cf + idx);
                    float2 mm = *(const float2*)(mul + idx);
                    *(float2*)(Cf + idx) = make_float2(cc.x + mm.x * a0,
                                                       cc.y + mm.y * a1);
                } else { // EP == 6 runtime
                    if (rt_ep == 2) {          // relu^2 -> half
                        float z0 = fmaxf(a0, 0.f), z1 = fmaxf(a1, 0.f);
                        *(__half2*)(Ch + idx) = __floats2half2_rn(z0 * z0, z1 * z1);
                    } else if (rt_ep == 4) {   // silu -> half
                        float s0 = a0 / (1.f + expf(-a0));
                        float s1 = a1 / (1.f + expf(-a1));
                        *(__half2*)(Ch + idx) = __floats2half2_rn(s0, s1);
                    } else {
                        float2 o;
                        if (rt_ep == 1)      { o.x = a0 / (1.f + expf(-a0));
                                               o.y = a1 / (1.f + expf(-a1)); }
                        else if (rt_ep == 3) { o.x = 1.f / (1.f + expf(-a0));
                                               o.y = 1.f / (1.f + expf(-a1)); }
                        else                 { o.x = a0; o.y = a1; }
                        *(float2*)(Cf + idx) = o;
                    }
                }
            }
        }
    }
}

template<int EP>
__global__ __launch_bounds__(256, 1) void gemm_f16(
    const __half* __restrict__ A, const __half* __restrict__ B,
    void* __restrict__ C, int M, int N, int K,
    const float* __restrict__ res, const float* __restrict__ mul)
{
    extern __shared__ __half smem[];
    gemm_core<EP>(A, B, C, M, N, K, res, mul, 0, smem,
                  blockIdx.y * 128, blockIdx.x * 256);
}

// 4 projection GEMMs in one launch; z in {0,1,2} none->f32, z==3 silu->half
__global__ __launch_bounds__(256, 1) void gemm_proj4(
    const __half* __restrict__ A0, const __half* __restrict__ A1,
    const __half* __restrict__ A2, const __half* __restrict__ A3,
    const __half* __restrict__ B0, const __half* __restrict__ B1,
    const __half* __restrict__ B2, const __half* __restrict__ B3,
    float* __restrict__ C0, float* __restrict__ C1,
    float* __restrict__ C2, __half* __restrict__ C3)
{
    extern __shared__ __half smem[];
    const __half* A; const __half* Bw; void* C; int ep;
    int z = blockIdx.z;
    if (z == 0)      { A = A0; Bw = B0; C = C0; ep = 0; }
    else if (z == 1) { A = A1; Bw = B1; C = C1; ep = 0; }
    else if (z == 2) { A = A2; Bw = B2; C = C2; ep = 0; }
    else             { A = A3; Bw = B3; C = C3; ep = 4; }
    gemm_core<6>(A, Bw, C, Mv, Cv, Cv, nullptr, nullptr, ep,
                 smem, blockIdx.y * 128, blockIdx.x * 256);
}

// FFN-K (relu^2 -> half, N=3584) + FFN-R (sigmoid -> f32, N=1024)
__global__ __launch_bounds__(256, 1) void gemm_ffnpair(
    const __half* __restrict__ Ak, const __half* __restrict__ Bk, __half* __restrict__ Ck,
    const __half* __restrict__ Ar, const __half* __restrict__ Br, float* __restrict__ Cr)
{
    extern __shared__ __half smem[];
    const int TK = FFNv / 256;
    if ((int)blockIdx.x < TK)
        gemm_core<6>(Ak, Bk, Ck, Mv, FFNv, Cv, nullptr, nullptr, 2,
                     smem, blockIdx.y * 128, blockIdx.x * 256);
    else
        gemm_core<6>(Ar, Br, Cr, Mv, Cv, Cv, nullptr, nullptr, 3,
                     smem, blockIdx.y * 128, (blockIdx.x - TK) * 256);
}

// ---------------------------------------------------------------------------
// WKV5 recurrence (r8 proven: fp32 inputs, CH=8)
// ---------------------------------------------------------------------------
__global__ __launch_bounds__(256) void wkv_kernel(
    const float* __restrict__ r, const float* __restrict__ k,
    const float* __restrict__ v,
    const float* __restrict__ decay, const float* __restrict__ faaaa,
    float* __restrict__ y)
{
    const int CH = 8;
    __shared__ float sr[CH][Nv], sk[CH][Nv], sv[CH][Nv];

    int bh = blockIdx.x;
    int b = bh / Hv, h = bh % Hv;
    int tid = threadIdx.x;
    int j  = tid >> 2;
    int gq = tid & 3;
    int ib = gq * 16;

    float S[16], ew[16], uu[16];
#pragma unroll
    for (int ii = 0; ii < 16; ii++) {
        S[ii]  = 0.f;
        ew[ii] = expf(-expf(decay[h * Nv + ib + ii]));
        uu[ii] = faaaa[h * Nv + ib + ii];
    }

    size_t base = ((size_t)b * Tv) * Cv + (size_t)h * Nv;

    for (int tc = 0; tc < Tv; tc += CH) {
        __syncthreads();
        for (int idx = tid; idx < CH * Nv; idx += 256) {
            int st = idx >> 6, c = idx & 63;
            size_t off = base + (size_t)(tc + st) * Cv + c;
            sr[st][c] = r[off];
            sk[st][c] = k[off];
            sv[st][c] = v[off];
        }
        __syncthreads();

#pragma unroll
        for (int st = 0; st < CH; st++) {
            float vj = sv[st][j];
            float y0 = 0.f;
#pragma unroll
            for (int ii = 0; ii < 16; ii++) {
                float ri = sr[st][ib + ii];
                float ki = sk[st][ib + ii];
                float t = ki * vj;
                y0 = fmaf(ri, fmaf(uu[ii], t, S[ii]), y0);
                S[ii] = fmaf(ew[ii], S[ii], t);
            }
            y0 += __shfl_xor_sync(0xffffffffu, y0, 1);
            y0 += __shfl_xor_sync(0xffffffffu, y0, 2);
            if (gq == 0)
                y[base + (size_t)(tc + st) * Cv + j] = y0;
        }
    }
}

// ---------------------------------------------------------------------------
// GroupNorm * gate(half) -> half output
// ---------------------------------------------------------------------------
__global__ __launch_bounds__(256) void gnmul_kernel(
    const float* __restrict__ y, const __half* __restrict__ g,
    const float* __restrict__ w, const float* __restrict__ b,
    __half* __restrict__ ym)
{
    int m = blockIdx.x, tid = threadIdx.x;
    size_t base = (size_t)m * Cv;
    float4 v = ((const float4*)(y + base))[tid];
    const float s8 = 1.0f / 8.0f;
    v.x *= s8; v.y *= s8; v.z *= s8; v.w *= s8;

    float s  = v.x + v.y + v.z + v.w;
    float ss = v.x*v.x + v.y*v.y + v.z*v.z + v.w*v.w;
#pragma unroll
    for (int o = 8; o; o >>= 1) {
        s  += __shfl_xor_sync(0xffffffffu, s,  o);
        ss += __shfl_xor_sync(0xffffffffu, ss, o);
    }
    float mu  = s * (1.0f / Nv);
    float var = ss * (1.0f / Nv) - mu * mu;
    float inv = rsqrtf(var + EPSv);

    float4 wv = ((const float4*)w)[tid];
    float4 bv = ((const float4*)b)[tid];
    uint2 gu = *(const uint2*)(g + base + (size_t)tid * 4);
    __half2 g01 = *reinterpret_cast<__half2*>(&gu.x);
    __half2 g23 = *reinterpret_cast<__half2*>(&gu.y);
    float4 gv = make_float4(__low2float(g01), __high2float(g01),
                            __low2float(g23), __high2float(g23));
    float4 o;
    o.x = ((v.x - mu) * inv * wv.x + bv.x) * gv.x;
    o.y = ((v.y - mu) * inv * wv.y + bv.y) * gv.y;
    o.z = ((v.z - mu) * inv * wv.z + bv.z) * gv.z;
    o.w = ((v.w - mu) * inv * wv.w + bv.w) * gv.w;
    st_half4(ym, base / 4 + tid, o);
}

// ---------------------------------------------------------------------------
// launch
// ---------------------------------------------------------------------------
#define GEMM_SMEM (3 * (128 * 72 + 256 * 72) * 2)   /* 165,888 B */

extern "C" void kernel_launch(void* const* d_in, const int* in_sizes, int n_in,
                              void* d_out, int out_size)
{
    const float* x        = (const float*)d_in[0];
    const float* ln0_w    = (const float*)d_in[1];
    const float* ln0_b    = (const float*)d_in[2];
    const float* ln1_w    = (const float*)d_in[3];
    const float* ln1_b    = (const float*)d_in[4];
    const float* ln2_w    = (const float*)d_in[5];
    const float* ln2_b    = (const float*)d_in[6];
    const float* att_tmk  = (const float*)d_in[7];
    const float* att_tmv  = (const float*)d_in[8];
    const float* att_tmr  = (const float*)d_in[9];
    const float* att_tmg  = (const float*)d_in[10];
    const float* att_decay  = (const float*)d_in[11];
    const float* att_faaaa  = (const float*)d_in[12];
    const float* att_Wr   = (const float*)d_in[13];
    const float* att_Wk   = (const float*)d_in[14];
    const float* att_Wv   = (const float*)d_in[15];
    const float* att_Wg   = (const float*)d_in[16];
    const float* att_Wo   = (const float*)d_in[17];
    const float* att_lnx_w = (const float*)d_in[18];
    const float* att_lnx_b = (const float*)d_in[19];
    const float* ffn_tmk  = (const float*)d_in[20];
    const float* ffn_tmr  = (const float*)d_in[21];
    const float* ffn_Wk   = (const float*)d_in[22];
    const float* ffn_Wr   = (const float*)d_in[23];
    const float* ffn_Wv   = (const float*)d_in[24];
    float* out = (float*)d_out;

    void* poolv = nullptr;
    cudaGetSymbolAddress(&poolv, g_pool);
    float* pool = (float*)poolv;

    float*  bx0  = pool + OFF_X0;
    __half* bxr  = (__half*)(pool + OFF_XR);
    __half* bxk  = (__half*)(pool + OFF_XK);
    __half* bxv  = (__half*)(pool + OFF_XV);
    __half* bxg  = (__half*)(pool + OFF_XG);
    float*  br   = pool + OFF_R;
    float*  bk   = pool + OFF_K;
    float*  bv   = pool + OFF_V;
    __half* bg   = (__half*)(pool + OFF_G);
    float*  by   = pool + OFF_Y;
    __half* bym  = (__half*)(pool + OFF_YM);
    __half* bxk2 = (__half*)(pool + OFF_XK2);
    __half* bxr2 = (__half*)(pool + OFF_XR2);
    float*  bsr  = pool + OFF_SR;
    __half* bkf  = (__half*)(pool + OFF_KF);
    __half* wWr  = (__half*)(pool + OFF_WR);
    __half* wWk  = (__half*)(pool + OFF_WK);
    __half* wWv  = (__half*)(pool + OFF_WV);
    __half* wWg  = (__half*)(pool + OFF_WG);
    __half* wWo  = (__half*)(pool + OFF_WO);
    __half* wFWr = (__half*)(pool + OFF_FWR);
    __half* wFWk = (__half*)(pool + OFF_FWK);
    __half* wFWv = (__half*)(pool + OFF_FWV);

    cudaFuncSetAttribute(gemm_f16<4>,  cudaFuncAttributeMaxDynamicSharedMemorySize, GEMM_SMEM);
    cudaFuncSetAttribute(gemm_f16<5>,  cudaFuncAttributeMaxDynamicSharedMemorySize, GEMM_SMEM);
    cudaFuncSetAttribute(gemm_proj4,   cudaFuncAttributeMaxDynamicSharedMemorySize, GEMM_SMEM);
    cudaFuncSetAttribute(gemm_ffnpair, cudaFuncAttributeMaxDynamicSharedMemorySize, GEMM_SMEM);

    // all weight conversions in one launch
    const int nCC4 = (int)(WCC / 4), nFC4 = (int)(WFC / 4);
    dim3 gW((nFC4 + 255) / 256, 1, 8);
    cvtw_all_kernel<<<gW, 256>>>(att_Wr, att_Wk, att_Wv, att_Wg, att_Wo, ffn_Wr,
                                 ffn_Wk, ffn_Wv,
                                 wWr, wWk, wWv, wWg, wWo, wFWr, wFWk, wFWv,
                                 nCC4, nFC4);

    // attention path
    ln01mix4_kernel<<<Mv, 256>>>(x, ln0_w, ln0_b, ln1_w, ln1_b,
                                 att_tmk, att_tmv, att_tmr, att_tmg,
                                 bx0, bxk, bxv, bxr, bxg);
    dim3 gP(Cv / 256, Mv / 128, 4);
    gemm_proj4<<<gP, 256, GEMM_SMEM>>>(bxr, bxk, bxv, bxg,
                                       wWr, wWk, wWv, wWg,
                                       br, bk, bv, bg);
    wkv_kernel<<<Bv * Hv, 256>>>(br, bk, bv, att_decay, att_faaaa, by);
    gnmul_kernel<<<Mv, 256>>>(by, bg, att_lnx_w, att_lnx_b, bym);
    dim3 gC(Cv / 256, Mv / 128);
    gemm_f16<4><<<gC, 256, GEMM_SMEM>>>(bym, wWo, out, Mv, Cv, Cv, bx0, nullptr);

    // channel-mix path
    ln2mix2_kernel<<<Mv, 256>>>(out, ln2_w, ln2_b, ffn_tmk, ffn_tmr, bxk2, bxr2);
    dim3 gPair(FFNv / 256 + Cv / 256, Mv / 128);
    gemm_ffnpair<<<gPair, 256, GEMM_SMEM>>>(bxk2, wFWk, bkf, bxr2, wFWr, bsr);
    gemm_f16<5><<<gC, 256, GEMM_SMEM>>>(bkf, wFWv, out, Mv, Cv, FFNv, nullptr, bsr);
}

// round 16
// speedup vs baseline: 1.4645x; 1.0403x over previous
#include <cuda_runtime.h>
#include <cuda_fp16.h>
#include <cstdint>
#include <math.h>

#define Bv   8
#define Tv   2048
#define Cv   1024
#define Hv   16
#define Nv   64
#define FFNv 3584
#define Mv   (Bv*Tv)          /* 16384 tokens */
#define EPSv 1e-5f

// ---------------------------------------------------------------------------
// Scratch pool
// ---------------------------------------------------------------------------
#define MC   ((size_t)Mv * Cv)
#define MF   ((size_t)Mv * FFNv)
#define WCC  ((size_t)Cv * Cv)
#define WFC  ((size_t)FFNv * Cv)
__device__ float g_pool[16 * MC + MF + 6 * WCC + 2 * WFC];

#define OFF_X0   (0*MC)
#define OFF_XR   (2*MC)
#define OFF_XK   (3*MC)
#define OFF_XV   (4*MC)
#define OFF_XG   (5*MC)
#define OFF_R    (6*MC)
#define OFF_K    (7*MC)
#define OFF_V    (8*MC)
#define OFF_G    (9*MC)
#define OFF_Y    (10*MC)
#define OFF_YM   (11*MC)
#define OFF_XK2  (13*MC)
#define OFF_XR2  (14*MC)
#define OFF_SR   (15*MC)
#define OFF_KF   (16*MC)
#define OFF_W    (16*MC + MF)
#define OFF_WR   (OFF_W + 0*WCC)
#define OFF_WK   (OFF_W + 1*WCC)
#define OFF_WV   (OFF_W + 2*WCC)
#define OFF_WG   (OFF_W + 3*WCC)
#define OFF_WO   (OFF_W + 4*WCC)
#define OFF_FWR  (OFF_W + 5*WCC)
#define OFF_FWK  (OFF_W + 6*WCC)
#define OFF_FWV  (OFF_W + 6*WCC + WFC)

// ---------------------------------------------------------------------------
// helpers
// ---------------------------------------------------------------------------
__device__ __forceinline__ float4 block_reduce4(float a, float b, float c, float d,
                                                float* shm /*32*/)
{
#pragma unroll
    for (int o = 16; o; o >>= 1) {
        a += __shfl_xor_sync(0xffffffffu, a, o);
        b += __shfl_xor_sync(0xffffffffu, b, o);
        c += __shfl_xor_sync(0xffffffffu, c, o);
        d += __shfl_xor_sync(0xffffffffu, d, o);
    }
    int w = threadIdx.x >> 5;
    if ((threadIdx.x & 31) == 0) { shm[w] = a; shm[8+w] = b; shm[16+w] = c; shm[24+w] = d; }
    __syncthreads();
    a = shm[0]; b = shm[8]; c = shm[16]; d = shm[24];
#pragma unroll
    for (int i = 1; i < 8; i++) {
        a += shm[i]; b += shm[8+i]; c += shm[16+i]; d += shm[24+i];
    }
    return make_float4(a, b, c, d);
}

__device__ __forceinline__ void st_half4(__half* p, size_t i4, float4 v)
{
    __half2 lo = __floats2half2_rn(v.x, v.y);
    __half2 hi = __floats2half2_rn(v.z, v.w);
    uint2 u;
    u.x = *reinterpret_cast<unsigned*>(&lo);
    u.y = *reinterpret_cast<unsigned*>(&hi);
    *reinterpret_cast<uint2*>(p + i4 * 4) = u;
}

__device__ __forceinline__ void cp_async16(void* smem, const void* gptr)
{
    unsigned saddr = (unsigned)__cvta_generic_to_shared(smem);
    asm volatile("cp.async.ca.shared.global [%0], [%1], 16;\n" :: "r"(saddr), "l"(gptr));
}
#define CP_COMMIT() asm volatile("cp.async.commit_group;\n" ::: "memory")
#define CP_WAIT0()  asm volatile("cp.async.wait_group 0;\n" ::: "memory")
#define CP_WAIT1()  asm volatile("cp.async.wait_group 1;\n" ::: "memory")

#define LDSM4(r0, r1, r2, r3, addr) \
    asm volatile("ldmatrix.sync.aligned.m8n8.x4.shared.b16 {%0,%1,%2,%3}, [%4];" \
                 : "=r"(r0), "=r"(r1), "=r"(r2), "=r"(r3) : "r"(addr))

// ---------------------------------------------------------------------------
// all weights fp32 -> fp16 in one launch
// ---------------------------------------------------------------------------
__global__ __launch_bounds__(256) void cvtw_all_kernel(
    const float* __restrict__ i0, const float* __restrict__ i1,
    const float* __restrict__ i2, const float* __restrict__ i3,
    const float* __restrict__ i4, const float* __restrict__ i5,
    const float* __restrict__ i6, const float* __restrict__ i7,
    __half* __restrict__ o0, __half* __restrict__ o1,
    __half* __restrict__ o2, __half* __restrict__ o3,
    __half* __restrict__ o4, __half* __restrict__ o5,
    __half* __restrict__ o6, __half* __restrict__ o7,
    int nCC4, int nFC4)
{
    int z = blockIdx.z;
    const float* in; __half* outp; int n4;
    switch (z) {
        case 0: in = i0; outp = o0; n4 = nCC4; break;
        case 1: in = i1; outp = o1; n4 = nCC4; break;
        case 2: in = i2; outp = o2; n4 = nCC4; break;
        case 3: in = i3; outp = o3; n4 = nCC4; break;
        case 4: in = i4; outp = o4; n4 = nCC4; break;
        case 5: in = i5; outp = o5; n4 = nCC4; break;
        case 6: in = i6; outp = o6; n4 = nFC4; break;
        default: in = i7; outp = o7; n4 = nFC4; break;
    }
    int idx = blockIdx.x * blockDim.x + threadIdx.x;
    if (idx >= n4) return;
    float4 v = ((const float4*)in)[idx];
    st_half4(outp, idx, v);
}

// ---------------------------------------------------------------------------
// Fused LN0+LN1+token-shift-mix4 -> half outputs
// ---------------------------------------------------------------------------
__global__ __launch_bounds__(256) void ln01mix4_kernel(
    const float* __restrict__ x,
    const float* __restrict__ w0, const float* __restrict__ b0,
    const float* __restrict__ w1, const float* __restrict__ b1,
    const float* __restrict__ tmk, const float* __restrict__ tmv,
    const float* __restrict__ tmr, const float* __restrict__ tmg,
    float* __restrict__ x0,
    __half* __restrict__ xk, __half* __restrict__ xv,
    __half* __restrict__ xr, __half* __restrict__ xg)
{
    __shared__ float shm1[32], shm2[32];
    int m = blockIdx.x, tid = threadIdx.x;
    bool hp = (m % Tv) != 0;

    const float4 vc = ((const float4*)(x + (size_t)m * Cv))[tid];
    float4 vp = make_float4(0.f, 0.f, 0.f, 0.f);
    if (hp) vp = ((const float4*)(x + (size_t)(m - 1) * Cv))[tid];

    float4 r0 = block_reduce4(
        vc.x + vc.y + vc.z + vc.w,
        vc.x*vc.x + vc.y*vc.y + vc.z*vc.z + vc.w*vc.w,
        vp.x + vp.y + vp.z + vp.w,
        vp.x*vp.x + vp.y*vp.y + vp.z*vp.z + vp.w*vp.w, shm1);

    float muc = r0.x * (1.0f / Cv);
    float ivc = rsqrtf(r0.y * (1.0f / Cv) - muc * muc + EPSv);
    float mup = r0.z * (1.0f / Cv);
    float ivp = rsqrtf(r0.w * (1.0f / Cv) - mup * mup + EPSv);

    const float4 w0v = ((const float4*)w0)[tid];
    const float4 b0v = ((const float4*)b0)[tid];
    float4 c0, p0;
    c0.x = (vc.x - muc) * ivc * w0v.x + b0v.x;
    c0.y = (vc.y - muc) * ivc * w0v.y + b0v.y;
    c0.z = (vc.z - muc) * ivc * w0v.z + b0v.z;
    c0.w = (vc.w - muc) * ivc * w0v.w + b0v.w;
    p0.x = (vp.x - mup) * ivp * w0v.x + b0v.x;
    p0.y = (vp.y - mup) * ivp * w0v.y + b0v.y;
    p0.z = (vp.z - mup) * ivp * w0v.z + b0v.z;
    p0.w = (vp.w - mup) * ivp * w0v.w + b0v.w;
    ((float4*)(x0 + (size_t)m * Cv))[tid] = c0;

    float4 r1 = block_reduce4(
        c0.x + c0.y + c0.z + c0.w,
        c0.x*c0.x + c0.y*c0.y + c0.z*c0.z + c0.w*c0.w,
        p0.x + p0.y + p0.z + p0.w,
        p0.x*p0.x + p0.y*p0.y + p0.z*p0.z + p0.w*p0.w, shm2);

    muc = r1.x * (1.0f / Cv);
    ivc = rsqrtf(r1.y * (1.0f / Cv) - muc * muc + EPSv);
    mup = r1.z * (1.0f / Cv);
    ivp = rsqrtf(r1.w * (1.0f / Cv) - mup * mup + EPSv);

    const float4 w1v = ((const float4*)w1)[tid];
    const float4 b1v = ((const float4*)b1)[tid];
    float4 xnc, xnp;
    xnc.x = (c0.x - muc) * ivc * w1v.x + b1v.x;
    xnc.y = (c0.y - muc) * ivc * w1v.y + b1v.y;
    xnc.z = (c0.z - muc) * ivc * w1v.z + b1v.z;
    xnc.w = (c0.w - muc) * ivc * w1v.w + b1v.w;
    if (hp) {
        xnp.x = (p0.x - mup) * ivp * w1v.x + b1v.x;
        xnp.y = (p0.y - mup) * ivp * w1v.y + b1v.y;
        xnp.z = (p0.z - mup) * ivp * w1v.z + b1v.z;
        xnp.w = (p0.w - mup) * ivp * w1v.w + b1v.w;
    } else {
        xnp = make_float4(0.f, 0.f, 0.f, 0.f);
    }
    float4 dd = make_float4(xnc.x - xnp.x, xnc.y - xnp.y,
                            xnc.z - xnp.z, xnc.w - xnp.w);
    size_t idx = (size_t)m * (Cv / 4) + tid;

#define DO_MIX(TM, OUT) { \
    float4 w = ((const float4*)TM)[tid]; \
    float4 o; \
    o.x = fmaf(dd.x, w.x, xnp.x); o.y = fmaf(dd.y, w.y, xnp.y); \
    o.z = fmaf(dd.z, w.z, xnp.z); o.w = fmaf(dd.w, w.w, xnp.w); \
    st_half4(OUT, idx, o); }

    DO_MIX(tmk, xk)
    DO_MIX(tmv, xv)
    DO_MIX(tmr, xr)
    DO_MIX(tmg, xg)
#undef DO_MIX
}

// ---------------------------------------------------------------------------
// Fused LN2+token-shift-mix2 -> half outputs
// ---------------------------------------------------------------------------
__global__ __launch_bounds__(256) void ln2mix2_kernel(
    const float* __restrict__ in,
    const float* __restrict__ w2, const float* __restrict__ b2,
    const float* __restrict__ tmk, const float* __restrict__ tmr,
    __half* __restrict__ xk, __half* __restrict__ xr)
{
    __shared__ float shm[32];
    int m = blockIdx.x, tid = threadIdx.x;
    bool hp = (m % Tv) != 0;

    const float4 vc = ((const float4*)(in + (size_t)m * Cv))[tid];
    float4 vp = make_float4(0.f, 0.f, 0.f, 0.f);
    if (hp) vp = ((const float4*)(in + (size_t)(m - 1) * Cv))[tid];

    float4 r0 = block_reduce4(
        vc.x + vc.y + vc.z + vc.w,
        vc.x*vc.x + vc.y*vc.y + vc.z*vc.z + vc.w*vc.w,
        vp.x + vp.y + vp.z + vp.w,
        vp.x*vp.x + vp.y*vp.y + vp.z*vp.z + vp.w*vp.w, shm);

    float muc = r0.x * (1.0f / Cv);
    float ivc = rsqrtf(r0.y * (1.0f / Cv) - muc * muc + EPSv);
    float mup = r0.z * (1.0f / Cv);
    float ivp = rsqrtf(r0.w * (1.0f / Cv) - mup * mup + EPSv);

    const float4 wv = ((const float4*)w2)[tid];
    const float4 bv = ((const float4*)b2)[tid];
    float4 xnc, xnp;
    xnc.x = (vc.x - muc) * ivc * wv.x + bv.x;
    xnc.y = (vc.y - muc) * ivc * wv.y + bv.y;
    xnc.z = (vc.z - muc) * ivc * wv.z + bv.z;
    xnc.w = (vc.w - muc) * ivc * wv.w + bv.w;
    if (hp) {
        xnp.x = (vp.x - mup) * ivp * wv.x + bv.x;
        xnp.y = (vp.y - mup) * ivp * wv.y + bv.y;
        xnp.z = (vp.z - mup) * ivp * wv.z + bv.z;
        xnp.w = (vp.w - mup) * ivp * wv.w + bv.w;
    } else {
        xnp = make_float4(0.f, 0.f, 0.f, 0.f);
    }
    float4 dd = make_float4(xnc.x - xnp.x, xnc.y - xnp.y,
                            xnc.z - xnp.z, xnc.w - xnp.w);
    size_t idx = (size_t)m * (Cv / 4) + tid;

#define DO_MIX(TM, OUT) { \
    float4 w = ((const float4*)TM)[tid]; \
    float4 o; \
    o.x = fmaf(dd.x, w.x, xnp.x); o.y = fmaf(dd.y, w.y, xnp.y); \
    o.z = fmaf(dd.z, w.z, xnp.z); o.w = fmaf(dd.w, w.w, xnp.w); \
    st_half4(OUT, idx, o); }

    DO_MIX(tmk, xk)
    DO_MIX(tmr, xr)
#undef DO_MIX
}

// ---------------------------------------------------------------------------
// FP16 tensor-core NT GEMM core (r8 proven).
// EP: 4 +res(f32 out), 5 C(f32) += mul(f32)*acc,
//     6 runtime {0 none->f32, 1 silu->f32, 2 relu^2->half, 3 sigmoid->f32,
//                4 silu->half}
// ---------------------------------------------------------------------------
template<int EP>
__device__ __forceinline__ void gemm_core(
    const __half* __restrict__ A, const __half* __restrict__ B,
    void* __restrict__ Cp, int M, int N, int K,
    const float* __restrict__ res, const float* __restrict__ mul,
    int rt_ep, __half* smem, int bm, int bn)
{
    const int BM = 128, BN = 256, BK = 64, P = 72;
    __half* As = smem;
    __half* Bs = smem + 3 * BM * P;

    const int tid  = threadIdx.x;
    const int wid  = tid >> 5;
    const int lane = tid & 31;
    const int warp_m = (wid & 1) * 64;
    const int warp_n = (wid >> 1) * 64;
    const int gr = lane >> 2;
    const int gc = lane & 3;

    const __half* Abase = A + (size_t)bm * K;
    const __half* Bbase = B + (size_t)bn * K;

    const unsigned asmem = (unsigned)__cvta_generic_to_shared(As);
    const unsigned bsmem = (unsigned)__cvta_generic_to_shared(Bs);
    const unsigned aoff = asmem + (unsigned)(((warp_m + (lane & 15)) * P + ((lane & 16) >> 1)) * 2);
    const unsigned boff = bsmem + (unsigned)(((warp_n + (lane & 7) + ((lane & 16) >> 1)) * P + (lane & 8)) * 2);
    const unsigned BUFA = BM * P * 2;
    const unsigned BUFB = BN * P * 2;
    const unsigned R16  = 16 * P * 2;

    const int arow = tid >> 3;
    const int aseg = tid & 7;

#define PREFETCH(kt, buf) { \
    int k0 = (kt) * BK; \
    _Pragma("unroll") \
    for (int c = 0; c < 4; c++) { \
        int row = arow + c * 32; \
        cp_async16(As + (buf) * BM * P + row * P + aseg * 8, \
                   Abase + (size_t)row * K + k0 + aseg * 8); \
    } \
    _Pragma("unroll") \
    for (int c = 0; c < 8; c++) { \
        int row = arow + c * 32; \
        cp_async16(Bs + (buf) * BN * P + row * P + aseg * 8, \
                   Bbase + (size_t)row * K + k0 + aseg * 8); \
    } \
    CP_COMMIT(); }

    float acc[4][8][4];
#pragma unroll
    for (int mt = 0; mt < 4; mt++)
#pragma unroll
        for (int nt = 0; nt < 8; nt++)
#pragma unroll
            for (int q = 0; q < 4; q++) acc[mt][nt][q] = 0.f;

    const int NT = K / BK;
    PREFETCH(0, 0)
    PREFETCH(1, 1)

    int buf = 0;
    for (int kt = 0; kt < NT; kt++) {
        if (kt + 1 < NT) { CP_WAIT1(); } else { CP_WAIT0(); }
        __syncthreads();
        int nbuf = buf + 2; if (nbuf >= 3) nbuf -= 3;
        if (kt + 2 < NT) PREFETCH(kt + 2, nbuf)

        const unsigned ab = aoff + buf * BUFA;
        const unsigned bb = boff + buf * BUFB;
#pragma unroll
        for (int kk = 0; kk < BK; kk += 16) {
            uint32_t af[4][4], bf[8][2];
#pragma unroll
            for (int mt = 0; mt < 4; mt++)
                LDSM4(af[mt][0], af[mt][1], af[mt][2], af[mt][3],
                      ab + mt * R16 + kk * 2);
#pragma unroll
            for (int p = 0; p < 4; p++)
                LDSM4(bf[2*p][0], bf[2*p][1], bf[2*p+1][0], bf[2*p+1][1],
                      bb + p * R16 + kk * 2);
#pragma unroll
            for (int mt = 0; mt < 4; mt++)
#pragma unroll
                for (int nt = 0; nt < 8; nt++) {
                    asm volatile(
                        "mma.sync.aligned.m16n8k16.row.col.f32.f16.f16.f32 "
                        "{%0,%1,%2,%3}, {%4,%5,%6,%7}, {%8,%9}, {%0,%1,%2,%3};"
                        : "+f"(acc[mt][nt][0]), "+f"(acc[mt][nt][1]),
                          "+f"(acc[mt][nt][2]), "+f"(acc[mt][nt][3])
                        : "r"(af[mt][0]), "r"(af[mt][1]), "r"(af[mt][2]), "r"(af[mt][3]),
                          "r"(bf[nt][0]), "r"(bf[nt][1]));
                }
        }
        buf = buf + 1; if (buf >= 3) buf -= 3;
    }
#undef PREFETCH

    float* Cf = (float*)Cp;
    __half* Ch = (__half*)Cp;
#pragma unroll
    for (int mt = 0; mt < 4; mt++) {
#pragma unroll
        for (int nt = 0; nt < 8; nt++) {
            int row = bm + warp_m + mt * 16 + gr;
            int col = bn + warp_n + nt * 8 + 2 * gc;
#pragma unroll
            for (int half_ = 0; half_ < 2; half_++) {
                size_t idx = (size_t)(row + half_ * 8) * N + col;
                float a0 = acc[mt][nt][half_ * 2 + 0];
                float a1 = acc[mt][nt][half_ * 2 + 1];
                if (EP == 4) {
                    float2 rr = *(const float2*)(res + idx);
                    *(float2*)(Cf + idx) = make_float2(a0 + rr.x, a1 + rr.y);
                } else if (EP == 5) {
                    float2 cc = *(const float2*)(Cf + idx);
                    float2 mm = *(const float2*)(mul + idx);
                    *(float2*)(Cf + idx) = make_float2(cc.x + mm.x * a0,
                                                       cc.y + mm.y * a1);
                } else { // EP == 6 runtime
                    if (rt_ep == 2) {          // relu^2 -> half
                        float z0 = fmaxf(a0, 0.f), z1 = fmaxf(a1, 0.f);
                        *(__half2*)(Ch + idx) = __floats2half2_rn(z0 * z0, z1 * z1);
                    } else if (rt_ep == 4) {   // silu -> half
                        float s0 = a0 / (1.f + expf(-a0));
                        float s1 = a1 / (1.f + expf(-a1));
                        *(__half2*)(Ch + idx) = __floats2half2_rn(s0, s1);
                    } else {
                        float2 o;
                        if (rt_ep == 1)      { o.x = a0 / (1.f + expf(-a0));
                                               o.y = a1 / (1.f + expf(-a1)); }
                        else if (rt_ep == 3) { o.x = 1.f / (1.f + expf(-a0));
                                               o.y = 1.f / (1.f + expf(-a1)); }
                        else                 { o.x = a0; o.y = a1; }
                        *(float2*)(Cf + idx) = o;
                    }
                }
            }
        }
    }
}

template<int EP>
__global__ __launch_bounds__(256, 1) void gemm_f16(
    const __half* __restrict__ A, const __half* __restrict__ B,
    void* __restrict__ C, int M, int N, int K,
    const float* __restrict__ res, const float* __restrict__ mul)
{
    extern __shared__ __half smem[];
    gemm_core<EP>(A, B, C, M, N, K, res, mul, 0, smem,
                  blockIdx.y * 128, blockIdx.x * 256);
}

// 4 projection GEMMs in one launch; z in {0,1,2} none->f32, z==3 silu->half
__global__ __launch_bounds__(256, 1) void gemm_proj4(
    const __half* __restrict__ A0, const __half* __restrict__ A1,
    const __half* __restrict__ A2, const __half* __restrict__ A3,
    const __half* __restrict__ B0, const __half* __restrict__ B1,
    const __half* __restrict__ B2, const __half* __restrict__ B3,
    float* __restrict__ C0, float* __restrict__ C1,
    float* __restrict__ C2, __half* __restrict__ C3)
{
    extern __shared__ __half smem[];
    const __half* A; const __half* Bw; void* C; int ep;
    int z = blockIdx.z;
    if (z == 0)      { A = A0; Bw = B0; C = C0; ep = 0; }
    else if (z == 1) { A = A1; Bw = B1; C = C1; ep = 0; }
    else if (z == 2) { A = A2; Bw = B2; C = C2; ep = 0; }
    else             { A = A3; Bw = B3; C = C3; ep = 4; }
    gemm_core<6>(A, Bw, C, Mv, Cv, Cv, nullptr, nullptr, ep,
                 smem, blockIdx.y * 128, blockIdx.x * 256);
}

// FFN-K (relu^2 -> half, N=3584) + FFN-R (sigmoid -> f32, N=1024)
__global__ __launch_bounds__(256, 1) void gemm_ffnpair(
    const __half* __restrict__ Ak, const __half* __restrict__ Bk, __half* __restrict__ Ck,
    const __half* __restrict__ Ar, const __half* __restrict__ Br, float* __restrict__ Cr)
{
    extern __shared__ __half smem[];
    const int TK = FFNv / 256;
    if ((int)blockIdx.x < TK)
        gemm_core<6>(Ak, Bk, Ck, Mv, FFNv, Cv, nullptr, nullptr, 2,
                     smem, blockIdx.y * 128, blockIdx.x * 256);
    else
        gemm_core<6>(Ar, Br, Cr, Mv, Cv, Cv, nullptr, nullptr, 3,
                     smem, blockIdx.y * 128, (blockIdx.x - TK) * 256);
}

// ---------------------------------------------------------------------------
// WKV5 recurrence, j-split 4-way: block = (b,h,jq); jq owns j in
// [jq*16, jq*16+16). 256 threads: j = j0 + (tid>>4), gq = tid&15,
// per-thread i-slab = gq*4 .. gq*4+3 (S[4]). Reduce over 16 lanes.
// ---------------------------------------------------------------------------
__global__ __launch_bounds__(256) void wkv_kernel(
    const float* __restrict__ r, const float* __restrict__ k,
    const float* __restrict__ v,
    const float* __restrict__ decay, const float* __restrict__ faaaa,
    float* __restrict__ y)
{
    const int CH = 8;
    __shared__ float sr[CH][Nv], sk[CH][Nv], sv[CH][16];

    int blk = blockIdx.x;
    int jq = blk & 3;
    int bh = blk >> 2;
    int b = bh / Hv, h = bh % Hv;
    int j0 = jq * 16;

    int tid = threadIdx.x;
    int jl  = tid >> 4;          // 0..15 local j
    int gq  = tid & 15;          // i-slab selector
    int ib  = gq * 4;

    float S[4], ew[4], uu[4];
#pragma unroll
    for (int ii = 0; ii < 4; ii++) {
        S[ii]  = 0.f;
        ew[ii] = expf(-expf(decay[h * Nv + ib + ii]));
        uu[ii] = faaaa[h * Nv + ib + ii];
    }

    size_t base = ((size_t)b * Tv) * Cv + (size_t)h * Nv;

    for (int tc = 0; tc < Tv; tc += CH) {
        __syncthreads();
        // stage r,k: CH*64 = 512 entries, 2 per thread
        for (int idx = tid; idx < CH * Nv; idx += 256) {
            int st = idx >> 6, c = idx & 63;
            size_t off = base + (size_t)(tc + st) * Cv + c;
            sr[st][c] = r[off];
            sk[st][c] = k[off];
        }
        // stage v: CH*16 = 128 entries (only owned j-range)
        if (tid < CH * 16) {
            int st = tid >> 4, c = tid & 15;
            sv[st][c] = v[base + (size_t)(tc + st) * Cv + j0 + c];
        }
        __syncthreads();

#pragma unroll
        for (int st = 0; st < CH; st++) {
            float vj = sv[st][jl];
            float y0 = 0.f;
#pragma unroll
            for (int ii = 0; ii < 4; ii++) {
                float ri = sr[st][ib + ii];
                float ki = sk[st][ib + ii];
                float t = ki * vj;
                y0 = fmaf(ri, fmaf(uu[ii], t, S[ii]), y0);
                S[ii] = fmaf(ew[ii], S[ii], t);
            }
            y0 += __shfl_xor_sync(0xffffffffu, y0, 1);
            y0 += __shfl_xor_sync(0xffffffffu, y0, 2);
            y0 += __shfl_xor_sync(0xffffffffu, y0, 4);
            y0 += __shfl_xor_sync(0xffffffffu, y0, 8);
            if (gq == 0)
                y[base + (size_t)(tc + st) * Cv + j0 + jl] = y0;
        }
    }
}

// ---------------------------------------------------------------------------
// GroupNorm * gate(half) -> half output
// ---------------------------------------------------------------------------
__global__ __launch_bounds__(256) void gnmul_kernel(
    const float* __restrict__ y, const __half* __restrict__ g,
    const float* __restrict__ w, const float* __restrict__ b,
    __half* __restrict__ ym)
{
    int m = blockIdx.x, tid = threadIdx.x;
    size_t base = (size_t)m * Cv;
    float4 v = ((const float4*)(y + base))[tid];
    const float s8 = 1.0f / 8.0f;
    v.x *= s8; v.y *= s8; v.z *= s8; v.w *= s8;

    float s  = v.x + v.y + v.z + v.w;
    float ss = v.x*v.x + v.y*v.y + v.z*v.z + v.w*v.w;
#pragma unroll
    for (int o = 8; o; o >>= 1) {
        s  += __shfl_xor_sync(0xffffffffu, s,  o);
        ss += __shfl_xor_sync(0xffffffffu, ss, o);
    }
    float mu  = s * (1.0f / Nv);
    float var = ss * (1.0f / Nv) - mu * mu;
    float inv = rsqrtf(var + EPSv);

    float4 wv = ((const float4*)w)[tid];
    float4 bv = ((const float4*)b)[tid];
    uint2 gu = *(const uint2*)(g + base + (size_t)tid * 4);
    __half2 g01 = *reinterpret_cast<__half2*>(&gu.x);
    __half2 g23 = *reinterpret_cast<__half2*>(&gu.y);
    float4 gv = make_float4(__low2float(g01), __high2float(g01),
                            __low2float(g23), __high2float(g23));
    float4 o;
    o.x = ((v.x - mu) * inv * wv.x + bv.x) * gv.x;
    o.y = ((v.y - mu) * inv * wv.y + bv.y) * gv.y;
    o.z = ((v.z - mu) * inv * wv.z + bv.z) * gv.z;
    o.w = ((v.w - mu) * inv * wv.w + bv.w) * gv.w;
    st_half4(ym, base / 4 + tid, o);
}

// ---------------------------------------------------------------------------
// launch
// ---------------------------------------------------------------------------
#define GEMM_SMEM (3 * (128 * 72 + 256 * 72) * 2)   /* 165,888 B */

extern "C" void kernel_launch(void* const* d_in, const int* in_sizes, int n_in,
                              void* d_out, int out_size)
{
    const float* x        = (const float*)d_in[0];
    const float* ln0_w    = (const float*)d_in[1];
    const float* ln0_b    = (const float*)d_in[2];
    const float* ln1_w    = (const float*)d_in[3];
    const float* ln1_b    = (const float*)d_in[4];
    const float* ln2_w    = (const float*)d_in[5];
    const float* ln2_b    = (const float*)d_in[6];
    const float* att_tmk  = (const float*)d_in[7];
    const float* att_tmv  = (const float*)d_in[8];
    const float* att_tmr  = (const float*)d_in[9];
    const float* att_tmg  = (const float*)d_in[10];
    const float* att_decay  = (const float*)d_in[11];
    const float* att_faaaa  = (const float*)d_in[12];
    const float* att_Wr   = (const float*)d_in[13];
    const float* att_Wk   = (const float*)d_in[14];
    const float* att_Wv   = (const float*)d_in[15];
    const float* att_Wg   = (const float*)d_in[16];
    const float* att_Wo   = (const float*)d_in[17];
    const float* att_lnx_w = (const float*)d_in[18];
    const float* att_lnx_b = (const float*)d_in[19];
    const float* ffn_tmk  = (const float*)d_in[20];
    const float* ffn_tmr  = (const float*)d_in[21];
    const float* ffn_Wk   = (const float*)d_in[22];
    const float* ffn_Wr   = (const float*)d_in[23];
    const float* ffn_Wv   = (const float*)d_in[24];
    float* out = (float*)d_out;

    void* poolv = nullptr;
    cudaGetSymbolAddress(&poolv, g_pool);
    float* pool = (float*)poolv;

    float*  bx0  = pool + OFF_X0;
    __half* bxr  = (__half*)(pool + OFF_XR);
    __half* bxk  = (__half*)(pool + OFF_XK);
    __half* bxv  = (__half*)(pool + OFF_XV);
    __half* bxg  = (__half*)(pool + OFF_XG);
    float*  br   = pool + OFF_R;
    float*  bk   = pool + OFF_K;
    float*  bv   = pool + OFF_V;
    __half* bg   = (__half*)(pool + OFF_G);
    float*  by   = pool + OFF_Y;
    __half* bym  = (__half*)(pool + OFF_YM);
    __half* bxk2 = (__half*)(pool + OFF_XK2);
    __half* bxr2 = (__half*)(pool + OFF_XR2);
    float*  bsr  = pool + OFF_SR;
    __half* bkf  = (__half*)(pool + OFF_KF);
    __half* wWr  = (__half*)(pool + OFF_WR);
    __half* wWk  = (__half*)(pool + OFF_WK);
    __half* wWv  = (__half*)(pool + OFF_WV);
    __half* wWg  = (__half*)(pool + OFF_WG);
    __half* wWo  = (__half*)(pool + OFF_WO);
    __half* wFWr = (__half*)(pool + OFF_FWR);
    __half* wFWk = (__half*)(pool + OFF_FWK);
    __half* wFWv = (__half*)(pool + OFF_FWV);

    cudaFuncSetAttribute(gemm_f16<4>,  cudaFuncAttributeMaxDynamicSharedMemorySize, GEMM_SMEM);
    cudaFuncSetAttribute(gemm_f16<5>,  cudaFuncAttributeMaxDynamicSharedMemorySize, GEMM_SMEM);
    cudaFuncSetAttribute(gemm_proj4,   cudaFuncAttributeMaxDynamicSharedMemorySize, GEMM_SMEM);
    cudaFuncSetAttribute(gemm_ffnpair, cudaFuncAttributeMaxDynamicSharedMemorySize, GEMM_SMEM);

    // all weight conversions in one launch
    const int nCC4 = (int)(WCC / 4), nFC4 = (int)(WFC / 4);
    dim3 gW((nFC4 + 255) / 256, 1, 8);
    cvtw_all_kernel<<<gW, 256>>>(att_Wr, att_Wk, att_Wv, att_Wg, att_Wo, ffn_Wr,
                                 ffn_Wk, ffn_Wv,
                                 wWr, wWk, wWv, wWg, wWo, wFWr, wFWk, wFWv,
                                 nCC4, nFC4);

    // attention path
    ln01mix4_kernel<<<Mv, 256>>>(x, ln0_w, ln0_b, ln1_w, ln1_b,
                                 att_tmk, att_tmv, att_tmr, att_tmg,
                                 bx0, bxk, bxv, bxr, bxg);
    dim3 gP(Cv / 256, Mv / 128, 4);
    gemm_proj4<<<gP, 256, GEMM_SMEM>>>(bxr, bxk, bxv, bxg,
                                       wWr, wWk, wWv, wWg,
                                       br, bk, bv, bg);
    wkv_kernel<<<Bv * Hv * 4, 256>>>(br, bk, bv, att_decay, att_faaaa, by);
    gnmul_kernel<<<Mv, 256>>>(by, bg, att_lnx_w, att_lnx_b, bym);
    dim3 gC(Cv / 256, Mv / 128);
    gemm_f16<4><<<gC, 256, GEMM_SMEM>>>(bym, wWo, out, Mv, Cv, Cv, bx0, nullptr);

    // channel-mix path
    ln2mix2_kernel<<<Mv, 256>>>(out, ln2_w, ln2_b, ffn_tmk, ffn_tmr, bxk2, bxr2);
    dim3 gPair(FFNv / 256 + Cv / 256, Mv / 128);
    gemm_ffnpair<<<gPair, 256, GEMM_SMEM>>>(bxk2, wFWk, bkf, bxr2, wFWr, bsr);
    gemm_f16<5><<<gC, 256, GEMM_SMEM>>>(bkf, wFWv, out, Mv, Cv, FFNv, nullptr, bsr);
}